// round 4
// baseline (speedup 1.0000x reference)
#include <cuda_runtime.h>
#include <cuda_bf16.h>
#include <cstdint>

// DotAttentionEluX: the reference math collapses.
//   attn[i,j] = ks_j / sum_j ks_j   (query cancels in the row normalization)
//   out[b,h,i,d] = (sum_j ks_j * v[b,h,j,d]) / (sum_j ks_j)  -- same for all i
// where ks_j = sum_d (elu(k[b,h,j,d]) + 1).
//
// Kernel 1 (accum): reduce K,V -> 16 x (num[64], den) partials per (b,h).
// Kernel 2 (bcast): finish the reduction, broadcast-write the 16 MB output.

static constexpr int B_ = 4, H_ = 8, L_ = 2048, D_ = 64;
static constexpr int BH = B_ * H_;          // 32
static constexpr int NSPLIT = 16;           // row splits per (b,h)
static constexpr int ROWS_PER_SPLIT = L_ / NSPLIT;  // 128
static constexpr int WARPS = 8;

// Scratch: per-(bh,split) partial numerators and denominators.
// Written (not accumulated) every call -> no zeroing kernel needed.
__device__ float g_num[BH * NSPLIT * D_];
__device__ float g_den[BH * NSPLIT];

__device__ __forceinline__ float elu1(float x) {
    return x > 0.0f ? x + 1.0f : __expf(x);
}

__global__ __launch_bounds__(256) void accum_kernel(
    const float* __restrict__ K, const float* __restrict__ V)
{
    const int blk   = blockIdx.x;       // 0..BH*NSPLIT-1
    const int bh    = blk / NSPLIT;
    const int split = blk % NSPLIT;
    const int warp  = threadIdx.x >> 5; // 0..7
    const int lane  = threadIdx.x & 31;

    // This warp's first row within (b,h); rows advance by WARPS.
    const size_t base = ((size_t)bh * L_ + (size_t)split * ROWS_PER_SPLIT + warp) * D_
                        + (size_t)lane * 2;
    const float* __restrict__ Kp = K + base;
    const float* __restrict__ Vp = V + base;
    constexpr int STRIDE = WARPS * D_;                  // elements between rows
    constexpr int NROWS  = ROWS_PER_SPLIT / WARPS;      // 16 rows per warp

    float n0 = 0.0f, n1 = 0.0f, den = 0.0f;

    #pragma unroll
    for (int r = 0; r < NROWS; r++) {
        // Issue both loads before the shuffle chain: 2 LDGs in flight per iter.
        float2 kk = *reinterpret_cast<const float2*>(Kp + (size_t)r * STRIDE);
        float2 vv = *reinterpret_cast<const float2*>(Vp + (size_t)r * STRIDE);
        float ks = elu1(kk.x) + elu1(kk.y);
        #pragma unroll
        for (int o = 16; o; o >>= 1)
            ks += __shfl_xor_sync(0xffffffffu, ks, o);
        n0 += ks * vv.x;
        n1 += ks * vv.y;
        if (lane == 0) den += ks;
    }

    __shared__ float s_num[WARPS][D_];
    __shared__ float s_den[WARPS];
    s_num[warp][lane * 2]     = n0;
    s_num[warp][lane * 2 + 1] = n1;
    if (lane == 0) s_den[warp] = den;
    __syncthreads();

    const int t = threadIdx.x;
    if (t < D_) {
        float s = 0.0f;
        #pragma unroll
        for (int w = 0; w < WARPS; w++) s += s_num[w][t];
        g_num[(bh * NSPLIT + split) * D_ + t] = s;
    }
    if (t == D_) {
        float s = 0.0f;
        #pragma unroll
        for (int w = 0; w < WARPS; w++) s += s_den[w];
        g_den[bh * NSPLIT + split] = s;
    }
}

static constexpr int CHUNKS = 32;                  // row chunks per (b,h)
static constexpr int ROWS_PER_CHUNK = L_ / CHUNKS; // 64 rows per CTA

__global__ __launch_bounds__(256) void bcast_kernel(float* __restrict__ out)
{
    const int chunk = blockIdx.x;   // 0..31
    const int bh    = blockIdx.y;   // 0..31
    const int t     = threadIdx.x;  // 256 threads

    __shared__ float4 s_w4[D_ / 4]; // w[64] viewed as 16 float4

    if (t < D_) {
        const float* __restrict__ pn = g_num + bh * NSPLIT * D_ + t;
        float num = 0.0f, den = 0.0f;
        #pragma unroll
        for (int sp = 0; sp < NSPLIT; sp++) {
            num += pn[sp * D_];
            den += g_den[bh * NSPLIT + sp];
        }
        reinterpret_cast<float*>(s_w4)[t] = num / den;
    }
    __syncthreads();

    // 64 rows * 16 float4/row = 1024 float4 stores; 256 threads x 4 each.
    float4* __restrict__ ob = reinterpret_cast<float4*>(
        out + ((size_t)bh * L_ + (size_t)chunk * ROWS_PER_CHUNK) * D_);
    #pragma unroll
    for (int i = 0; i < 4; i++) {
        const int idx = t + i * 256;      // 0..1023
        const int q   = idx & 15;         // float4 slot within a row
        ob[idx] = s_w4[q];
    }
}

extern "C" void kernel_launch(void* const* d_in, const int* in_sizes, int n_in,
                              void* d_out, int out_size)
{
    // metadata order: query, key, value. Query is mathematically irrelevant.
    const float* K = (const float*)d_in[1];
    const float* V = (const float*)d_in[2];
    float* out = (float*)d_out;

    accum_kernel<<<BH * NSPLIT, 256>>>(K, V);
    bcast_kernel<<<dim3(CHUNKS, BH), 256>>>(out);
}

// round 5
// speedup vs baseline: 1.0175x; 1.0175x over previous
#include <cuda_runtime.h>
#include <cuda_bf16.h>
#include <cstdint>

// DotAttentionEluX — math collapses:
//   attn[i,j] = ks_j / sum_j ks_j  (query cancels in row normalization)
//   out[b,h,i,:] = (sum_j ks_j * v_j) / (sum_j ks_j)   -- same for every row i
// with ks_j = sum_d (elu(k[b,h,j,d]) + 1).
//
// Kernel 1 (accum): reduce K,V -> 16 partials per (b,h).     [DRAM-read bound]
// Kernel 2 (bcast): finish reduction, replicate row into SMEM, then bulk-async
//   copy 32KB per CTA (R4 showed STG.128 issue cost was the bottleneck:
//   1M STG.128 @ ~12cyc/SMSP ~= 7.3us; TMA bulk path removes it).

static constexpr int B_ = 4, H_ = 8, L_ = 2048, D_ = 64;
static constexpr int BH = B_ * H_;                  // 32
static constexpr int NSPLIT = 16;
static constexpr int ROWS_PER_SPLIT = L_ / NSPLIT;  // 128
static constexpr int WARPS = 8;

__device__ float g_num[BH * NSPLIT * D_];
__device__ float g_den[BH * NSPLIT];

__device__ __forceinline__ float elu1(float x) {
    return x > 0.0f ? x + 1.0f : __expf(x);
}

__global__ __launch_bounds__(256) void accum_kernel(
    const float* __restrict__ K, const float* __restrict__ V)
{
    const int blk   = blockIdx.x;
    const int bh    = blk / NSPLIT;
    const int split = blk % NSPLIT;
    const int warp  = threadIdx.x >> 5;
    const int lane  = threadIdx.x & 31;

    const size_t base = ((size_t)bh * L_ + (size_t)split * ROWS_PER_SPLIT + warp) * D_
                        + (size_t)lane * 2;
    const float* __restrict__ Kp = K + base;
    const float* __restrict__ Vp = V + base;
    constexpr int STRIDE = WARPS * D_;
    constexpr int NROWS  = ROWS_PER_SPLIT / WARPS;   // 16 rows per warp

    float n0 = 0.0f, n1 = 0.0f, den = 0.0f;

    #pragma unroll
    for (int r = 0; r < NROWS; r++) {
        float2 kk = *reinterpret_cast<const float2*>(Kp + (size_t)r * STRIDE);
        float2 vv = *reinterpret_cast<const float2*>(Vp + (size_t)r * STRIDE);
        float ks = elu1(kk.x) + elu1(kk.y);
        #pragma unroll
        for (int o = 16; o; o >>= 1)
            ks += __shfl_xor_sync(0xffffffffu, ks, o);
        n0 += ks * vv.x;
        n1 += ks * vv.y;
        if (lane == 0) den += ks;
    }

    __shared__ float s_num[WARPS][D_];
    __shared__ float s_den[WARPS];
    s_num[warp][lane * 2]     = n0;
    s_num[warp][lane * 2 + 1] = n1;
    if (lane == 0) s_den[warp] = den;
    __syncthreads();

    const int t = threadIdx.x;
    if (t < D_) {
        float s = 0.0f;
        #pragma unroll
        for (int w = 0; w < WARPS; w++) s += s_num[w][t];
        g_num[(bh * NSPLIT + split) * D_ + t] = s;
    }
    if (t == D_) {
        float s = 0.0f;
        #pragma unroll
        for (int w = 0; w < WARPS; w++) s += s_den[w];
        g_den[bh * NSPLIT + split] = s;
    }
}

// ---- bcast: 16 chunks x 32 bh = 512 CTAs, each bulk-stores 32 KB ----
static constexpr int NCHUNK = 16;
static constexpr int ROWS_PER_CHUNK = L_ / NCHUNK;        // 128 rows
static constexpr int CHUNK_BYTES = ROWS_PER_CHUNK * D_ * 4; // 32768

__global__ __launch_bounds__(128) void bcast_kernel(float* __restrict__ out)
{
    const int chunk = blockIdx.x;   // 0..15
    const int bh    = blockIdx.y;   // 0..31
    const int t     = threadIdx.x;  // 128 threads

    __shared__ alignas(128) float4 s_buf[ROWS_PER_CHUNK * (D_ / 4)]; // 32 KB
    __shared__ float4 s_w4[D_ / 4];

    // Finish the split reduction (64 threads), w = num/den.
    if (t < D_) {
        const float* __restrict__ pn = g_num + bh * NSPLIT * D_ + t;
        float num = 0.0f, den = 0.0f;
        #pragma unroll
        for (int sp = 0; sp < NSPLIT; sp++) {
            num += pn[sp * D_];
            den += g_den[bh * NSPLIT + sp];
        }
        reinterpret_cast<float*>(s_w4)[t] = num / den;
    }
    __syncthreads();

    // Replicate the 256B row into all 128 rows of the staging buffer.
    // Thread t owns float4 slot (t&15) for rows (t>>4) + 8*i  -> warp stores
    // 2 contiguous rows per step: conflict-free STS.128.
    {
        const float4 v = s_w4[t & 15];
        const int r0 = t >> 4;           // 0..7
        #pragma unroll
        for (int i = 0; i < ROWS_PER_CHUNK / 8; i++) {   // 16 iters
            s_buf[(r0 + 8 * i) * (D_ / 4) + (t & 15)] = v;
        }
    }
    __syncthreads();

    // Bulk async store: one 32 KB SMEM->GMEM copy per CTA.
    if (t == 0) {
        asm volatile("fence.proxy.async.shared::cta;" ::: "memory");
        const float* gdst = out + ((size_t)bh * L_ + (size_t)chunk * ROWS_PER_CHUNK) * D_;
        uint32_t saddr = (uint32_t)__cvta_generic_to_shared(s_buf);
        asm volatile(
            "cp.async.bulk.global.shared::cta.bulk_group [%0], [%1], %2;"
            :: "l"(gdst), "r"(saddr), "r"((int)CHUNK_BYTES) : "memory");
        asm volatile("cp.async.bulk.commit_group;" ::: "memory");
        // Keep the CTA (and its SMEM) alive until the bulk copy has read SMEM.
        asm volatile("cp.async.bulk.wait_group.read 0;" ::: "memory");
    }
}

extern "C" void kernel_launch(void* const* d_in, const int* in_sizes, int n_in,
                              void* d_out, int out_size)
{
    // metadata order: query, key, value. Query is mathematically irrelevant.
    const float* K = (const float*)d_in[1];
    const float* V = (const float*)d_in[2];
    float* out = (float*)d_out;

    accum_kernel<<<BH * NSPLIT, 256>>>(K, V);
    bcast_kernel<<<dim3(NCHUNK, BH), 128>>>(out);
}